// round 5
// baseline (speedup 1.0000x reference)
#include <cuda_runtime.h>
#include <cstdint>

#define BATCH 16
#define NF 64
#define FIN 192
#define HW 4096
#define IM 64
#define STEPS 16
#define EPSV 1e-5f

#define EMB_SLICE (BATCH*NF*HW)           /* 4,194,304 */
#define N_CLIP (BATCH*3*HW)               /* 196,608   */
#define OFF_EMB N_CLIP
#define OFF_RAW (OFF_EMB + 17*EMB_SLICE)  /* 71,499,776 */

// ---- device scratch (static allocation; no cudaMalloc anywhere) ----
__device__ float g_w[BATCH*NF*FIN];       // w[b][o][c]
__device__ float g_bias[BATCH*NF];        // b[b][o]
__device__ float g_mu[BATCH*FIN];
__device__ float g_rs[BATCH*FIN];         // rsqrt(var+eps)
__device__ float g_sobel[BATCH*128*HW];   // [b][0..63]=sobelx, [64..127]=sobely (33.5 MB)

// packed f32x2 FMA (sm_100+)
__device__ __forceinline__ void ffma2(unsigned long long& d, unsigned long long a, unsigned long long b) {
    asm("fma.rn.f32x2 %0, %1, %2, %0;" : "+l"(d) : "l"(a), "l"(b));
}

// ---------------------------------------------------------------------------
// w[b][o*192+c]: Wk read EXACTLY ONCE (was 16x). 48 CTAs, 16 batch-accumulators.
__global__ void __launch_bounds__(256) k_weights(const float* __restrict__ lat,
                                                 const float* __restrict__ Wk,
                                                 const float* __restrict__ bk) {
    __shared__ float ls[BATCH][512];                  // 32 KB
    int tid = threadIdx.x;
    for (int i = tid; i < BATCH*512; i += 256) ls[i >> 9][i & 511] = lat[i];
    __syncthreads();
    int j = blockIdx.x * 256 + tid;                   // 0..12287
    float bkj = bk[j];
    float acc[BATCH];
#pragma unroll
    for (int b = 0; b < BATCH; b++) acc[b] = bkj;
#pragma unroll 4
    for (int k = 0; k < 512; k++) {
        float wv = Wk[(size_t)k*12288 + j];
#pragma unroll
        for (int b = 0; b < BATCH; b++) acc[b] += ls[b][k] * wv;   // ls broadcast
    }
#pragma unroll
    for (int b = 0; b < BATCH; b++) g_w[(size_t)b*12288 + j] = acc[b];
}

__global__ void k_bias(const float* __restrict__ lat, const float* __restrict__ Wb,
                       const float* __restrict__ bb) {
    __shared__ float ls[512];
    int b = blockIdx.x;
    int o = threadIdx.x;                      // 64 threads
    for (int k = o; k < 512; k += 64) ls[k] = lat[b*512 + k];
    __syncthreads();
    float acc = bb[o];
#pragma unroll 8
    for (int k = 0; k < 512; k++) acc += ls[k] * Wb[k*64 + o];
    g_bias[b*64 + o] = acc;
}

// emb slice 0 = out0: zeros except channel 0, pixel (32,32)=1. Split in two so the
// first k_gemm is launch index 5 (ncu capture is -s 5 -c 1 -> profiles k_gemm).
__global__ void k_init_half(float* __restrict__ emb0, int base) {
    int idx = base + blockIdx.x * 256 + threadIdx.x;
    int within = idx & (NF*HW - 1);           // c*4096 + px
    emb0[idx] = (within == (32*64 + 32)) ? 1.0f : 0.0f;
}

// ---------------------------------------------------------------------------
// 3-value block reduction over 512 threads (16 warps).
__device__ __forceinline__ void reduce3w(float& a, float& b, float& c,
                                         float (*red)[16], int tid) {
#pragma unroll
    for (int off = 16; off; off >>= 1) {
        a += __shfl_down_sync(0xffffffffu, a, off);
        b += __shfl_down_sync(0xffffffffu, b, off);
        c += __shfl_down_sync(0xffffffffu, c, off);
    }
    __syncthreads();
    int w = tid >> 5, l = tid & 31;
    if (l == 0) { red[0][w] = a; red[1][w] = b; red[2][w] = c; }
    __syncthreads();
    a = b = c = 0.f;
#pragma unroll
    for (int i = 0; i < 16; i++) { a += red[0][i]; b += red[1][i]; c += red[2][i]; }
}

// Per (b, source-channel): Sobel-x/y via 66x66 zero-padded smem image (branch-free),
// materialize sobel, produce mean + rsqrt(var+eps) for the 3 perception channels.
__global__ void __launch_bounds__(512) k_stats(const float* __restrict__ embt) {
    __shared__ float img[66*66];              // 17.4 KB, zero border
    __shared__ float red[3][16];
    int b = blockIdx.y, c = blockIdx.x, tid = threadIdx.x;
    const float* src = embt + ((size_t)(b*NF + c)) * HW;
    for (int i = tid; i < 66*66; i += 512) img[i] = 0.f;
    __syncthreads();
    for (int i = tid; i < HW; i += 512) {
        int y = i >> 6, x = i & 63;
        img[(y + 1)*66 + (x + 1)] = src[i];
    }
    __syncthreads();

    float vv[8], sxv[8], syv[8];
    float s0 = 0.f, s1 = 0.f, s2 = 0.f;
#pragma unroll
    for (int k = 0; k < 8; k++) {
        int px = k*512 + tid;
        int p = ((px >> 6) + 1)*66 + (px & 63) + 1;
        float na = img[p-67], nb = img[p-66], nc = img[p-65];
        float nd = img[p-1],  v  = img[p],    ne = img[p+1];
        float nf = img[p+65], ng = img[p+66], nh = img[p+67];
        float sx = (nc - na + 2.f*(ne - nd) + nh - nf) * 0.125f;
        float sy = (nf - na + 2.f*(ng - nb) + nh - nc) * 0.125f;
        vv[k] = v; sxv[k] = sx; syv[k] = sy;
        s0 += v; s1 += sx; s2 += sy;
    }
    float* gx = g_sobel + ((size_t)(b*128 + c)) * HW;
    float* gy = gx + (size_t)64*HW;
#pragma unroll
    for (int k = 0; k < 8; k++) { int px = k*512 + tid; gx[px] = sxv[k]; gy[px] = syv[k]; }

    reduce3w(s0, s1, s2, red, tid);
    const float inv = 1.0f / HW;
    float mu0 = s0*inv, mu1 = s1*inv, mu2 = s2*inv;

    float q0 = 0.f, q1 = 0.f, q2 = 0.f;   // two-pass variance, register-resident
#pragma unroll
    for (int k = 0; k < 8; k++) {
        float d0 = vv[k]  - mu0;  q0 += d0*d0;
        float d1 = sxv[k] - mu1;  q1 += d1*d1;
        float d2 = syv[k] - mu2;  q2 += d2*d2;
    }
    reduce3w(q0, q1, q2, red, tid);
    if (tid == 0) {
        int base = b*FIN + c;
        g_mu[base]       = mu0;  g_rs[base]       = rsqrtf(q0*inv + EPSV);
        g_mu[base + 64]  = mu1;  g_rs[base + 64]  = rsqrtf(q1*inv + EPSV);
        g_mu[base + 128] = mu2;  g_rs[base + 128] = rsqrtf(q2*inv + EPSV);
    }
}

// ---------------------------------------------------------------------------
// Per (batch, 128-pixel tile): C[128px,64o] = sum_c norm(p)[c,px] * w[o,c];
// out_new = out_old + leak*(C + bias); writes next emb slice.
__device__ __forceinline__ void load_tiles(const float* __restrict__ embt, int b, int px0,
                                           int c0, int tid, const float* __restrict__ mu,
                                           const float* __restrict__ rs,
                                           float av[8], float wv[4]) {
#pragma unroll
    for (int r = 0; r < 8; r++) {
        int lin = r*256 + tid;
        int cc = lin >> 7, p = lin & 127;
        int c = c0 + cc;
        const float* src = (c < 64) ? (embt + ((size_t)(b*NF + c))*HW)
                                    : (g_sobel + ((size_t)(b*128 + (c - 64)))*HW);
        float v = src[px0 + p];
        av[r] = (v - mu[c]) * rs[c];
    }
#pragma unroll
    for (int r = 0; r < 4; r++) {
        int lin = r*256 + tid;
        int o = lin >> 4, cc = lin & 15;
        wv[r] = g_w[((size_t)(b*NF + o))*FIN + c0 + cc];
    }
}

__device__ __forceinline__ void store_tiles(float (*a_s)[128], unsigned long long (*w_s)[64],
                                            const float av[8], const float wv[4], int tid) {
#pragma unroll
    for (int r = 0; r < 8; r++) {
        int lin = r*256 + tid;
        a_s[lin >> 7][lin & 127] = av[r];
    }
#pragma unroll
    for (int r = 0; r < 4; r++) {
        int lin = r*256 + tid;
        unsigned int u = __float_as_uint(wv[r]);
        w_s[lin & 15][lin >> 4] = ((unsigned long long)u << 32) | u;
    }
}

__global__ void __launch_bounds__(256) k_gemm(const float* __restrict__ embt,
                                              float* __restrict__ embt1,
                                              const float* __restrict__ leak_ptr) {
    __shared__ float a_s[2][16][128];                 // 16 KB
    __shared__ unsigned long long w_s[2][16][64];     // 16 KB
    int b = blockIdx.y;
    int px0 = blockIdx.x * 128;
    int tid = threadIdx.x;
    int tx = tid & 31, ty = tid >> 5;
    const float* mu = g_mu + b*FIN;
    const float* rs = g_rs + b*FIN;

    unsigned long long acc[16];
#pragma unroll
    for (int i = 0; i < 16; i++) acc[i] = 0ull;

    float av[8], wv[4];
    load_tiles(embt, b, px0, 0, tid, mu, rs, av, wv);
    store_tiles(a_s[0], w_s[0], av, wv, tid);
    __syncthreads();

    // one barrier per chunk: prefetch(global) -> compute(buf) -> store(buf^1) -> sync
    for (int ch = 0; ch < 12; ch++) {
        int buf = ch & 1;
        if (ch < 11) load_tiles(embt, b, px0, (ch + 1)*16, tid, mu, rs, av, wv);
#pragma unroll
        for (int kk = 0; kk < 16; kk++) {
            unsigned long long ap0 = *(const unsigned long long*)&a_s[buf][kk][2*tx];
            unsigned long long ap1 = *(const unsigned long long*)&a_s[buf][kk][64 + 2*tx];
#pragma unroll
            for (int o = 0; o < 8; o++) {
                unsigned long long wvv = w_s[buf][kk][ty*8 + o];
                ffma2(acc[o*2],     ap0, wvv);
                ffma2(acc[o*2 + 1], ap1, wvv);
            }
        }
        if (ch < 11) store_tiles(a_s[buf ^ 1], w_s[buf ^ 1], av, wv, tid);
        __syncthreads();
    }

    float leak = *leak_ptr;
    leak = fminf(fmaxf(leak, 0.001f), 1000.0f);
#pragma unroll
    for (int o = 0; o < 8; o++) {
        int oo = ty*8 + o;
        float bo = g_bias[b*NF + oo];
        const float2* oldp = (const float2*)(embt  + ((size_t)(b*NF + oo))*HW + px0);
        float2*       newp = (float2*)      (embt1 + ((size_t)(b*NF + oo))*HW + px0);
        float lo0 = __uint_as_float((unsigned)(acc[o*2]     & 0xffffffffu));
        float hi0 = __uint_as_float((unsigned)(acc[o*2]     >> 32));
        float lo1 = __uint_as_float((unsigned)(acc[o*2 + 1] & 0xffffffffu));
        float hi1 = __uint_as_float((unsigned)(acc[o*2 + 1] >> 32));
        float2 o0 = oldp[tx];       // pixels 2tx, 2tx+1
        float2 o1 = oldp[32 + tx];  // pixels 64+2tx, 65+2tx
        float2 n0, n1;
        n0.x = o0.x + leak*(lo0 + bo);
        n0.y = o0.y + leak*(hi0 + bo);
        n1.x = o1.x + leak*(lo1 + bo);
        n1.y = o1.y + leak*(hi1 + bo);
        newp[tx] = n0;
        newp[32 + tx] = n1;
    }
}

// clipped RGB + raw RGB from the final state
__global__ void k_final(const float* __restrict__ emb_final, float* __restrict__ out) {
    int idx = blockIdx.x * 256 + threadIdx.x;     // < 196608
    int b = idx / (3*HW);
    int rem = idx - b*3*HW;
    int c = rem >> 12;
    int px = rem & 4095;
    float v = emb_final[((size_t)(b*NF + c))*HW + px];
    out[(size_t)OFF_RAW + idx] = v;
    out[idx] = fminf(fmaxf(v, -1.0f), 1.0f);
}

// ---------------------------------------------------------------------------
extern "C" void kernel_launch(void* const* d_in, const int* in_sizes, int n_in,
                              void* d_out, int out_size) {
    const float* lat  = (const float*)d_in[0];
    const float* Wk   = (const float*)d_in[1];
    const float* bk   = (const float*)d_in[2];
    const float* Wb   = (const float*)d_in[3];
    const float* bb   = (const float*)d_in[4];
    const float* leak = (const float*)d_in[5];
    float* out = (float*)d_out;

    k_weights<<<48, 256>>>(lat, Wk, bk);                       // launch 0
    k_bias<<<16, 64>>>(lat, Wb, bb);                           // launch 1
    k_init_half<<<EMB_SLICE/512, 256>>>(out + OFF_EMB, 0);     // launch 2
    k_init_half<<<EMB_SLICE/512, 256>>>(out + OFF_EMB, EMB_SLICE/2); // launch 3

    for (int t = 0; t < STEPS; t++) {
        const float* et  = out + (size_t)OFF_EMB + (size_t)t * EMB_SLICE;
        float*       et1 = out + (size_t)OFF_EMB + (size_t)(t + 1) * EMB_SLICE;
        k_stats<<<dim3(64, 16), 512>>>(et);                    // launch 4, 6, ...
        k_gemm<<<dim3(32, 16), 256>>>(et, et1, leak);          // launch 5  <- ncu -s 5
    }
    k_final<<<N_CLIP/256, 256>>>(out + OFF_EMB + (size_t)16*EMB_SLICE, out);
}

// round 7
// speedup vs baseline: 1.5604x; 1.5604x over previous
#include <cuda_runtime.h>
#include <cuda_bf16.h>
#include <cstdint>

#define BATCH 16
#define NF 64
#define FIN 192
#define HW 4096
#define STEPS 16
#define EPSV 1e-5f

#define EMB_SLICE (BATCH*NF*HW)           /* 4,194,304 */
#define N_CLIP (BATCH*3*HW)               /* 196,608   */
#define OFF_EMB N_CLIP
#define OFF_RAW (OFF_EMB + 17*EMB_SLICE)

// ---- device scratch (static allocation; no cudaMalloc anywhere) ----
__device__ __align__(16) __nv_bfloat16 g_ahi[(size_t)BATCH*FIN*HW];  // normalized perception, hi
__device__ __align__(16) __nv_bfloat16 g_alo[(size_t)BATCH*FIN*HW];  // normalized perception, lo
__device__ __align__(16) __nv_bfloat16 g_whi[BATCH*NF*FIN];          // w hi  [b][o][c]
__device__ __align__(16) __nv_bfloat16 g_wlo[BATCH*NF*FIN];          // w lo
__device__ float g_bias[BATCH*NF];

// bf16 two-term split: x ~= hi + lo with |err| ~ 2^-16 |x|
__device__ __forceinline__ void bsplit(float x, __nv_bfloat16& h, __nv_bfloat16& l) {
    h = __float2bfloat16(x);
    l = __float2bfloat16(x - __bfloat162float(h));
}

// ---------------------------------------------------------------------------
// w[b][o*192+c] = lat[b]·Wk[:,j] + bk[j], split to bf16 hi/lo. Wk read once.
__global__ void __launch_bounds__(256) k_weights(const float* __restrict__ lat,
                                                 const float* __restrict__ Wk,
                                                 const float* __restrict__ bk) {
    __shared__ float ls[BATCH][512];                  // 32 KB
    int tid = threadIdx.x;
    for (int i = tid; i < BATCH*512; i += 256) ls[i >> 9][i & 511] = lat[i];
    __syncthreads();
    int j = blockIdx.x * 256 + tid;                   // 0..12287
    float bkj = bk[j];
    float acc[BATCH];
#pragma unroll
    for (int b = 0; b < BATCH; b++) acc[b] = bkj;
#pragma unroll 4
    for (int k = 0; k < 512; k++) {
        float wv = Wk[(size_t)k*12288 + j];
#pragma unroll
        for (int b = 0; b < BATCH; b++) acc[b] += ls[b][k] * wv;
    }
#pragma unroll
    for (int b = 0; b < BATCH; b++) {
        __nv_bfloat16 h, l;
        bsplit(acc[b], h, l);
        g_whi[(size_t)b*12288 + j] = h;
        g_wlo[(size_t)b*12288 + j] = l;
    }
}

__global__ void k_bias(const float* __restrict__ lat, const float* __restrict__ Wb,
                       const float* __restrict__ bb) {
    __shared__ float ls[512];
    int b = blockIdx.x;
    int o = threadIdx.x;                      // 64 threads
    for (int k = o; k < 512; k += 64) ls[k] = lat[b*512 + k];
    __syncthreads();
    float acc = bb[o];
#pragma unroll 8
    for (int k = 0; k < 512; k++) acc += ls[k] * Wb[k*64 + o];
    g_bias[b*64 + o] = acc;
}

// emb slice 0 = out0: zeros except channel 0, pixel (32,32)=1
__global__ void k_init_half(float* __restrict__ emb0, int base) {
    int idx = base + blockIdx.x * 256 + threadIdx.x;
    int within = idx & (NF*HW - 1);
    emb0[idx] = (within == (32*64 + 32)) ? 1.0f : 0.0f;
}

// ---------------------------------------------------------------------------
// 3-value block reduction over 512 threads; broadcasts result to all threads.
__device__ __forceinline__ void reduce3w(float& a, float& b, float& c,
                                         float (*red)[16], int tid) {
#pragma unroll
    for (int off = 16; off; off >>= 1) {
        a += __shfl_down_sync(0xffffffffu, a, off);
        b += __shfl_down_sync(0xffffffffu, b, off);
        c += __shfl_down_sync(0xffffffffu, c, off);
    }
    __syncthreads();
    int w = tid >> 5, l = tid & 31;
    if (l == 0) { red[0][w] = a; red[1][w] = b; red[2][w] = c; }
    __syncthreads();
    a = b = c = 0.f;
#pragma unroll
    for (int i = 0; i < 16; i++) { a += red[0][i]; b += red[1][i]; c += red[2][i]; }
}

// Per (b, source-channel): Sobel via 66x66 padded smem (branch-free), instance-norm
// stats, and DIRECT emission of the normalized perception as bf16 hi/lo (GEMM A).
__global__ void __launch_bounds__(512) k_stats(const float* __restrict__ embt) {
    __shared__ float img[66*66];
    __shared__ float red[3][16];
    int b = blockIdx.y, c = blockIdx.x, tid = threadIdx.x;
    const float* src = embt + ((size_t)(b*NF + c)) * HW;
    for (int i = tid; i < 66*66; i += 512) img[i] = 0.f;
    __syncthreads();
    for (int i = tid; i < HW; i += 512) {
        int y = i >> 6, x = i & 63;
        img[(y + 1)*66 + (x + 1)] = src[i];
    }
    __syncthreads();

    float vv[8], sxv[8], syv[8];
    float s0 = 0.f, s1 = 0.f, s2 = 0.f;
#pragma unroll
    for (int k = 0; k < 8; k++) {
        int px = k*512 + tid;
        int p = ((px >> 6) + 1)*66 + (px & 63) + 1;
        float na = img[p-67], nb = img[p-66], nc = img[p-65];
        float nd = img[p-1],  v  = img[p],    ne = img[p+1];
        float nf = img[p+65], ng = img[p+66], nh = img[p+67];
        float sx = (nc - na + 2.f*(ne - nd) + nh - nf) * 0.125f;
        float sy = (nf - na + 2.f*(ng - nb) + nh - nc) * 0.125f;
        vv[k] = v; sxv[k] = sx; syv[k] = sy;
        s0 += v; s1 += sx; s2 += sy;
    }
    reduce3w(s0, s1, s2, red, tid);
    const float inv = 1.0f / HW;
    float mu0 = s0*inv, mu1 = s1*inv, mu2 = s2*inv;

    float q0 = 0.f, q1 = 0.f, q2 = 0.f;
#pragma unroll
    for (int k = 0; k < 8; k++) {
        float d0 = vv[k]  - mu0;  q0 += d0*d0;
        float d1 = sxv[k] - mu1;  q1 += d1*d1;
        float d2 = syv[k] - mu2;  q2 += d2*d2;
    }
    reduce3w(q0, q1, q2, red, tid);
    float rs0 = rsqrtf(q0*inv + EPSV);
    float rs1 = rsqrtf(q1*inv + EPSV);
    float rs2 = rsqrtf(q2*inv + EPSV);

    size_t c0 = ((size_t)(b*FIN + c)) * HW;          // identity channel
    size_t c1 = c0 + (size_t)64*HW;                  // sobel-x channel
    size_t c2 = c0 + (size_t)128*HW;                 // sobel-y channel
#pragma unroll
    for (int k = 0; k < 8; k++) {
        int px = k*512 + tid;
        __nv_bfloat16 h, l;
        bsplit((vv[k]  - mu0)*rs0, h, l); g_ahi[c0+px] = h; g_alo[c0+px] = l;
        bsplit((sxv[k] - mu1)*rs1, h, l); g_ahi[c1+px] = h; g_alo[c1+px] = l;
        bsplit((syv[k] - mu2)*rs2, h, l); g_ahi[c2+px] = h; g_alo[c2+px] = l;
    }
}

// ---------------------------------------------------------------------------
// Tensor-core GEMM: D[px,o] = sum_c A[px,c]*W[o,c] via mma.sync m16n8k16 bf16,
// 3-term hi/lo split for ~fp32 accuracy. CTA = 128 px x 64 o x K=192.
// smem A: [k=16][px=128] rows (pad 136) -> ldmatrix.trans gives row-major A frags.
// smem W: [o=64][k=16] rows (pad 24)    -> ldmatrix gives col-major B frags.

__device__ __forceinline__ void ldsm4(unsigned r[4], uint32_t addr) {
    asm volatile("ldmatrix.sync.aligned.m8n8.x4.shared.b16 {%0,%1,%2,%3}, [%4];\n"
        : "=r"(r[0]), "=r"(r[1]), "=r"(r[2]), "=r"(r[3]) : "r"(addr));
}
__device__ __forceinline__ void ldsm4t(unsigned r[4], uint32_t addr) {
    asm volatile("ldmatrix.sync.aligned.m8n8.x4.trans.shared.b16 {%0,%1,%2,%3}, [%4];\n"
        : "=r"(r[0]), "=r"(r[1]), "=r"(r[2]), "=r"(r[3]) : "r"(addr));
}
__device__ __forceinline__ void mma16816(float c[4], const unsigned a[4],
                                         unsigned b0, unsigned b1) {
    asm volatile("mma.sync.aligned.m16n8k16.row.col.f32.bf16.bf16.f32 "
        "{%0,%1,%2,%3}, {%4,%5,%6,%7}, {%8,%9}, {%0,%1,%2,%3};\n"
        : "+f"(c[0]), "+f"(c[1]), "+f"(c[2]), "+f"(c[3])
        : "r"(a[0]), "r"(a[1]), "r"(a[2]), "r"(a[3]), "r"(b0), "r"(b1));
}

#define SA_ROW 136                 /* 128 px + 8 pad (bf16) per k-row */
#define SW_ROW 24                  /* 16 k + 8 pad (bf16) per o-row   */
#define SA_BUF (16*SA_ROW)         /* 2176 */
#define SW_BUF (64*SW_ROW)         /* 1536 */
#define SA_TOT (2*2*SA_BUF)        /* 8704 */
#define SW_TOT (2*2*SW_BUF)        /* 6144 */

__global__ void __launch_bounds__(256) k_gemm(const float* __restrict__ embt,
                                              float* __restrict__ embt1,
                                              const float* __restrict__ leak_ptr) {
    __shared__ __nv_bfloat16 sm[SA_TOT + SW_TOT];     // 29,696 B
    int b = blockIdx.y;
    int px0 = blockIdx.x * 128;
    int tid = threadIdx.x;
    int w = tid >> 5, l = tid & 31;

    float acc[8][4];
#pragma unroll
    for (int i = 0; i < 8; i++)
#pragma unroll
        for (int j = 0; j < 4; j++) acc[i][j] = 0.f;

    // staging lane roles
    int ak = tid & 15, aseg = tid >> 4;                         // A: k-row, 8-px segment
    int wo = (tid & 127) >> 1, wk8 = (tid & 1) * 8;             // W: o-row, k half
    const __nv_bfloat16* gW = (tid < 128) ? g_whi : g_wlo;
    int wprec = tid >> 7;                                       // 0=hi, 1=lo
    const __nv_bfloat16* gAh = g_ahi + ((size_t)(b*FIN + ak))*HW + px0 + aseg*8;
    const __nv_bfloat16* gAl = g_alo + ((size_t)(b*FIN + ak))*HW + px0 + aseg*8;
    const __nv_bfloat16* gWp = gW + (size_t)(b*NF + wo)*FIN + wk8;

    // ldmatrix lane addressing (element offsets)
    uint32_t smb = (uint32_t)__cvta_generic_to_shared(sm);
    int arow = ((l >> 4) & 1)*8 + (l & 7);                      // k-row within chunk
    int apx  = w*16 + ((l >> 3) & 1)*8;                         // px within CTA tile
    int wrow = ((l >> 4) & 1)*8 + (l & 7);                      // o-row within 16-group
    int wk   = ((l >> 3) & 1)*8;                                // k element offset

    uint4 rah, ral, rw;
    rah = *(const uint4*)gAh;                                   // chunk 0 prefetch
    ral = *(const uint4*)gAl;
    rw  = *(const uint4*)gWp;

    for (int ch = 0; ch < 12; ch++) {
        int buf = ch & 1;
        {   // store prefetched chunk into buf
            __nv_bfloat16* sa = sm + buf*2*SA_BUF;
            *(uint4*)(sa + ak*SA_ROW + aseg*8)          = rah;  // hi plane
            *(uint4*)(sa + SA_BUF + ak*SA_ROW + aseg*8) = ral;  // lo plane
            __nv_bfloat16* sw = sm + SA_TOT + buf*2*SW_BUF + wprec*SW_BUF;
            *(uint4*)(sw + wo*SW_ROW + wk8)             = rw;
        }
        __syncthreads();
        if (ch < 11) {                                          // prefetch next chunk
            rah = *(const uint4*)(gAh + (size_t)16*HW);
            ral = *(const uint4*)(gAl + (size_t)16*HW);
            rw  = *(const uint4*)(gWp + 16);
            gAh += (size_t)16*HW; gAl += (size_t)16*HW; gWp += 16;
        }
        // A fragments (trans: smem [k][px] -> row-major [px][k] frags)
        unsigned a_hi[4], a_lo[4];
        uint32_t aBase = smb + (uint32_t)((buf*2*SA_BUF) + arow*SA_ROW + apx)*2;
        ldsm4t(a_hi, aBase);
        ldsm4t(a_lo, aBase + (uint32_t)SA_BUF*2);
#pragma unroll
        for (int i = 0; i < 4; i++) {                           // n-tile pairs (2i, 2i+1)
            unsigned wh[4], wl[4];
            uint32_t wBase = smb + (uint32_t)(SA_TOT + buf*2*SW_BUF
                              + (i*16 + wrow)*SW_ROW + wk)*2;
            ldsm4(wh, wBase);
            ldsm4(wl, wBase + (uint32_t)SW_BUF*2);
            mma16816(acc[2*i],   a_hi, wh[0], wh[1]);
            mma16816(acc[2*i],   a_hi, wl[0], wl[1]);
            mma16816(acc[2*i],   a_lo, wh[0], wh[1]);
            mma16816(acc[2*i+1], a_hi, wh[2], wh[3]);
            mma16816(acc[2*i+1], a_hi, wl[2], wl[3]);
            mma16816(acc[2*i+1], a_lo, wh[2], wh[3]);
        }
        __syncthreads();
    }

    // epilogue: new = old + leak*(D + bias)
    float leak = *leak_ptr;
    leak = fminf(fmaxf(leak, 0.001f), 1000.0f);
    int mr = px0 + w*16 + (l >> 2);                             // C frag row (m), +8 for c2/c3
#pragma unroll
    for (int nt = 0; nt < 8; nt++) {
        int o = nt*8 + (l & 3)*2;                               // C frag cols o, o+1
        const float* po0 = embt  + (size_t)(b*NF + o)*HW;
        float*       pn0 = embt1 + (size_t)(b*NF + o)*HW;
        float bv0 = g_bias[b*NF + o];
        float bv1 = g_bias[b*NF + o + 1];
        pn0[mr]            = po0[mr]            + leak*(acc[nt][0] + bv0);
        pn0[mr + HW]       = po0[mr + HW]       + leak*(acc[nt][1] + bv1);
        pn0[mr + 8]        = po0[mr + 8]        + leak*(acc[nt][2] + bv0);
        pn0[mr + 8 + HW]   = po0[mr + 8 + HW]   + leak*(acc[nt][3] + bv1);
    }
}

// clipped RGB + raw RGB from the final state
__global__ void k_final(const float* __restrict__ emb_final, float* __restrict__ out) {
    int idx = blockIdx.x * 256 + threadIdx.x;     // < 196608
    int b = idx / (3*HW);
    int rem = idx - b*3*HW;
    int c = rem >> 12;
    int px = rem & 4095;
    float v = emb_final[((size_t)(b*NF + c))*HW + px];
    out[(size_t)OFF_RAW + idx] = v;
    out[idx] = fminf(fmaxf(v, -1.0f), 1.0f);
}

// ---------------------------------------------------------------------------
extern "C" void kernel_launch(void* const* d_in, const int* in_sizes, int n_in,
                              void* d_out, int out_size) {
    const float* lat  = (const float*)d_in[0];
    const float* Wk   = (const float*)d_in[1];
    const float* bk   = (const float*)d_in[2];
    const float* Wb   = (const float*)d_in[3];
    const float* bb   = (const float*)d_in[4];
    const float* leak = (const float*)d_in[5];
    float* out = (float*)d_out;

    k_weights<<<48, 256>>>(lat, Wk, bk);
    k_bias<<<16, 64>>>(lat, Wb, bb);
    k_init_half<<<EMB_SLICE/512, 256>>>(out + OFF_EMB, 0);
    k_init_half<<<EMB_SLICE/512, 256>>>(out + OFF_EMB, EMB_SLICE/2);

    for (int t = 0; t < STEPS; t++) {
        const float* et  = out + (size_t)OFF_EMB + (size_t)t * EMB_SLICE;
        float*       et1 = out + (size_t)OFF_EMB + (size_t)(t + 1) * EMB_SLICE;
        k_stats<<<dim3(64, 16), 512>>>(et);
        k_gemm<<<dim3(32, 16), 256>>>(et, et1, leak);
    }
    k_final<<<N_CLIP/256, 256>>>(out + OFF_EMB + (size_t)16*EMB_SLICE, out);
}

// round 9
// speedup vs baseline: 1.8690x; 1.1978x over previous
#include <cuda_runtime.h>
#include <cuda_bf16.h>
#include <cstdint>

#define BATCH 16
#define NF 64
#define FIN 192
#define HW 4096
#define STEPS 16
#define EPSV 1e-5f

#define EMB_SLICE (BATCH*NF*HW)           /* 4,194,304 */
#define N_CLIP (BATCH*3*HW)               /* 196,608   */
#define OFF_EMB N_CLIP
#define OFF_RAW (OFF_EMB + 17*EMB_SLICE)

// ---- device scratch (static allocation; no cudaMalloc anywhere) ----
__device__ __align__(16) __nv_bfloat16 g_ahi[(size_t)BATCH*FIN*HW];  // normalized perception, hi
__device__ __align__(16) __nv_bfloat16 g_alo[(size_t)BATCH*FIN*HW];  // normalized perception, lo
__device__ __align__(16) __nv_bfloat16 g_whi[BATCH*NF*FIN];          // w hi  [b][o][c]
__device__ __align__(16) __nv_bfloat16 g_wlo[BATCH*NF*FIN];          // w lo
__device__ float g_bias[BATCH*NF];

// bf16 two-term split: x ~= hi + lo with |err| ~ 2^-16 |x|
__device__ __forceinline__ void bsplit(float x, __nv_bfloat16& h, __nv_bfloat16& l) {
    h = __float2bfloat16(x);
    l = __float2bfloat16(x - __bfloat162float(h));
}

// ---------------------------------------------------------------------------
// emb slice 0 = out0: zeros except channel 0, pixel (32,32)=1.  (our launch #0)
__global__ void k_init(float* __restrict__ emb0) {
    int idx = blockIdx.x * 256 + threadIdx.x;
    int within = idx & (NF*HW - 1);
    emb0[idx] = (within == (32*64 + 32)) ? 1.0f : 0.0f;
}

// blocks 0..47: w[b][o*192+c] = lat[b]·Wk[:,j] + bk[j] (bf16 hi/lo, Wk read once)
// block  48   : bias[b][o]    = lat[b]·Wb[:,o] + bb[o]          (our launch #1)
__global__ void __launch_bounds__(256) k_weights(const float* __restrict__ lat,
                                                 const float* __restrict__ Wk,
                                                 const float* __restrict__ bk,
                                                 const float* __restrict__ Wb,
                                                 const float* __restrict__ bb) {
    __shared__ float ls[BATCH][512];                  // 32 KB
    int tid = threadIdx.x;
    for (int i = tid; i < BATCH*512; i += 256) ls[i >> 9][i & 511] = lat[i];
    __syncthreads();
    if (blockIdx.x < 48) {
        int j = blockIdx.x * 256 + tid;               // 0..12287
        float bkj = bk[j];
        float acc[BATCH];
#pragma unroll
        for (int b = 0; b < BATCH; b++) acc[b] = bkj;
#pragma unroll 4
        for (int k = 0; k < 512; k++) {
            float wv = Wk[(size_t)k*12288 + j];
#pragma unroll
            for (int b = 0; b < BATCH; b++) acc[b] += ls[b][k] * wv;
        }
#pragma unroll
        for (int b = 0; b < BATCH; b++) {
            __nv_bfloat16 h, l;
            bsplit(acc[b], h, l);
            g_whi[(size_t)b*12288 + j] = h;
            g_wlo[(size_t)b*12288 + j] = l;
        }
    } else {
#pragma unroll
        for (int r = 0; r < 4; r++) {
            int idx = r*256 + tid;                    // 0..1023
            int b = idx >> 6, o = idx & 63;
            float acc = bb[o];
#pragma unroll 8
            for (int k = 0; k < 512; k++) acc += ls[b][k] * Wb[k*64 + o];
            g_bias[idx] = acc;
        }
    }
}

// ---------------------------------------------------------------------------
// 3-value block reduction over 512 threads; broadcasts result to all threads.
__device__ __forceinline__ void reduce3w(float& a, float& b, float& c,
                                         float (*red)[16], int tid) {
#pragma unroll
    for (int off = 16; off; off >>= 1) {
        a += __shfl_down_sync(0xffffffffu, a, off);
        b += __shfl_down_sync(0xffffffffu, b, off);
        c += __shfl_down_sync(0xffffffffu, c, off);
    }
    __syncthreads();
    int w = tid >> 5, l = tid & 31;
    if (l == 0) { red[0][w] = a; red[1][w] = b; red[2][w] = c; }
    __syncthreads();
    a = b = c = 0.f;
#pragma unroll
    for (int i = 0; i < 16; i++) { a += red[0][i]; b += red[1][i]; c += red[2][i]; }
}

// Per (b, source-channel): Sobel via 66x66 padded smem (branch-free), instance-norm
// stats, direct emission of normalized perception as bf16 hi/lo.  (our launch #2)
__global__ void __launch_bounds__(512) k_stats(const float* __restrict__ embt) {
    __shared__ float img[66*66];
    __shared__ float red[3][16];
    int b = blockIdx.y, c = blockIdx.x, tid = threadIdx.x;
    const float* src = embt + ((size_t)(b*NF + c)) * HW;
    for (int i = tid; i < 66*66; i += 512) img[i] = 0.f;
    __syncthreads();
    for (int i = tid; i < HW; i += 512) {
        int y = i >> 6, x = i & 63;
        img[(y + 1)*66 + (x + 1)] = src[i];
    }
    __syncthreads();

    float vv[8], sxv[8], syv[8];
    float s0 = 0.f, s1 = 0.f, s2 = 0.f;
#pragma unroll
    for (int k = 0; k < 8; k++) {
        int px = k*512 + tid;
        int p = ((px >> 6) + 1)*66 + (px & 63) + 1;
        float na = img[p-67], nb = img[p-66], nc = img[p-65];
        float nd = img[p-1],  v  = img[p],    ne = img[p+1];
        float nf = img[p+65], ng = img[p+66], nh = img[p+67];
        float sx = (nc - na + 2.f*(ne - nd) + nh - nf) * 0.125f;
        float sy = (nf - na + 2.f*(ng - nb) + nh - nc) * 0.125f;
        vv[k] = v; sxv[k] = sx; syv[k] = sy;
        s0 += v; s1 += sx; s2 += sy;
    }
    reduce3w(s0, s1, s2, red, tid);
    const float inv = 1.0f / HW;
    float mu0 = s0*inv, mu1 = s1*inv, mu2 = s2*inv;

    float q0 = 0.f, q1 = 0.f, q2 = 0.f;
#pragma unroll
    for (int k = 0; k < 8; k++) {
        float d0 = vv[k]  - mu0;  q0 += d0*d0;
        float d1 = sxv[k] - mu1;  q1 += d1*d1;
        float d2 = syv[k] - mu2;  q2 += d2*d2;
    }
    reduce3w(q0, q1, q2, red, tid);
    float rs0 = rsqrtf(q0*inv + EPSV);
    float rs1 = rsqrtf(q1*inv + EPSV);
    float rs2 = rsqrtf(q2*inv + EPSV);

    size_t c0 = ((size_t)(b*FIN + c)) * HW;
    size_t c1 = c0 + (size_t)64*HW;
    size_t c2 = c0 + (size_t)128*HW;
#pragma unroll
    for (int k = 0; k < 8; k++) {
        int px = k*512 + tid;
        __nv_bfloat16 h, l;
        bsplit((vv[k]  - mu0)*rs0, h, l); g_ahi[c0+px] = h; g_alo[c0+px] = l;
        bsplit((sxv[k] - mu1)*rs1, h, l); g_ahi[c1+px] = h; g_alo[c1+px] = l;
        bsplit((syv[k] - mu2)*rs2, h, l); g_ahi[c2+px] = h; g_alo[c2+px] = l;
    }
}

// ---------------------------------------------------------------------------
// Tensor-core GEMM, CTA = 256 px x 64 o x K=192 (12 k16 chunks), 8 warps.
// Each warp owns m32 (two m16 frags) sharing W frags -> mma:ldsm = 48:12/chunk.
// 3-term hi/lo split. One __syncthreads per chunk (double buffered).

__device__ __forceinline__ void ldsm4(unsigned r[4], uint32_t addr) {
    asm volatile("ldmatrix.sync.aligned.m8n8.x4.shared.b16 {%0,%1,%2,%3}, [%4];\n"
        : "=r"(r[0]), "=r"(r[1]), "=r"(r[2]), "=r"(r[3]) : "r"(addr));
}
__device__ __forceinline__ void ldsm4t(unsigned r[4], uint32_t addr) {
    asm volatile("ldmatrix.sync.aligned.m8n8.x4.trans.shared.b16 {%0,%1,%2,%3}, [%4];\n"
        : "=r"(r[0]), "=r"(r[1]), "=r"(r[2]), "=r"(r[3]) : "r"(addr));
}
__device__ __forceinline__ void mma16816(float c[4], const unsigned a[4],
                                         unsigned b0, unsigned b1) {
    asm volatile("mma.sync.aligned.m16n8k16.row.col.f32.bf16.bf16.f32 "
        "{%0,%1,%2,%3}, {%4,%5,%6,%7}, {%8,%9}, {%0,%1,%2,%3};\n"
        : "+f"(c[0]), "+f"(c[1]), "+f"(c[2]), "+f"(c[3])
        : "r"(a[0]), "r"(a[1]), "r"(a[2]), "r"(a[3]), "r"(b0), "r"(b1));
}

#define MPX 256                    /* CTA pixel tile */
#define SA_ROW 264                 /* 256 px + 8 pad (bf16) per k-row */
#define SW_ROW 24                  /* 16 k + 8 pad (bf16) per o-row   */
#define SA_BUF (16*SA_ROW)         /* 4224 elems */
#define SW_BUF (64*SW_ROW)         /* 1536 elems */
#define SA_TOT (2*2*SA_BUF)        /* 16896 */
#define SW_TOT (2*2*SW_BUF)        /* 6144  */

__global__ void __launch_bounds__(256) k_gemm(const float* __restrict__ embt,
                                              float* __restrict__ embt1,
                                              const float* __restrict__ leak_ptr) {
    __shared__ __nv_bfloat16 sm[SA_TOT + SW_TOT];     // 46,080 B
    int b = blockIdx.y;
    int px0 = blockIdx.x * MPX;
    int tid = threadIdx.x;
    int w = tid >> 5, l = tid & 31;

    float acc[2][8][4];
#pragma unroll
    for (int t = 0; t < 2; t++)
#pragma unroll
        for (int i = 0; i < 8; i++)
#pragma unroll
            for (int j = 0; j < 4; j++) acc[t][i][j] = 0.f;

    // A staging: 16 rows x 256 px / 8 = 512 segs per plane; 2 per thread per plane
    int aseg0 = tid, aseg1 = tid + 256;
    int ar0 = aseg0 >> 5, ax0 = (aseg0 & 31)*8;
    int ar1 = aseg1 >> 5, ax1 = (aseg1 & 31)*8;
    const __nv_bfloat16* gAh0 = g_ahi + ((size_t)(b*FIN + ar0))*HW + px0 + ax0;
    const __nv_bfloat16* gAh1 = g_ahi + ((size_t)(b*FIN + ar1))*HW + px0 + ax1;
    const __nv_bfloat16* gAl0 = g_alo + ((size_t)(b*FIN + ar0))*HW + px0 + ax0;
    const __nv_bfloat16* gAl1 = g_alo + ((size_t)(b*FIN + ar1))*HW + px0 + ax1;
    // W staging: 64 o x 16 k x 2 planes / 8 = 256 segs; 1 per thread
    int wprec = tid >> 7;
    int wo = (tid & 127) >> 1, wk8 = (tid & 1) * 8;
    const __nv_bfloat16* gWp = ((wprec == 0) ? g_whi : g_wlo)
                               + (size_t)(b*NF + wo)*FIN + wk8;

    // ldmatrix lane addressing
    uint32_t smb = (uint32_t)__cvta_generic_to_shared(sm);
    int arow = ((l >> 4) & 1)*8 + (l & 7);            // k-row
    int apxl = ((l >> 3) & 1)*8;                      // px sub-offset
    int wrow = ((l >> 4) & 1)*8 + (l & 7);
    int wk   = ((l >> 3) & 1)*8;

    uint4 rah0, rah1, ral0, ral1, rw;
    rah0 = *(const uint4*)gAh0;  rah1 = *(const uint4*)gAh1;
    ral0 = *(const uint4*)gAl0;  ral1 = *(const uint4*)gAl1;
    rw   = *(const uint4*)gWp;

    for (int ch = 0; ch < 12; ch++) {
        int buf = ch & 1;
        {
            __nv_bfloat16* sa = sm + buf*2*SA_BUF;
            *(uint4*)(sa + ar0*SA_ROW + ax0)          = rah0;
            *(uint4*)(sa + ar1*SA_ROW + ax1)          = rah1;
            *(uint4*)(sa + SA_BUF + ar0*SA_ROW + ax0) = ral0;
            *(uint4*)(sa + SA_BUF + ar1*SA_ROW + ax1) = ral1;
            __nv_bfloat16* sw = sm + SA_TOT + buf*2*SW_BUF + wprec*SW_BUF;
            *(uint4*)(sw + wo*SW_ROW + wk8)           = rw;
        }
        __syncthreads();
        if (ch < 11) {
            gAh0 += (size_t)16*HW; gAh1 += (size_t)16*HW;
            gAl0 += (size_t)16*HW; gAl1 += (size_t)16*HW; gWp += 16;
            rah0 = *(const uint4*)gAh0;  rah1 = *(const uint4*)gAh1;
            ral0 = *(const uint4*)gAl0;  ral1 = *(const uint4*)gAl1;
            rw   = *(const uint4*)gWp;
        }
        unsigned a_hi[2][4], a_lo[2][4];
#pragma unroll
        for (int t = 0; t < 2; t++) {
            uint32_t aBase = smb + (uint32_t)((buf*2*SA_BUF)
                              + arow*SA_ROW + w*32 + t*16 + apxl)*2;
            ldsm4t(a_hi[t], aBase);
            ldsm4t(a_lo[t], aBase + (uint32_t)SA_BUF*2);
        }
#pragma unroll
        for (int i = 0; i < 4; i++) {
            unsigned wh[4], wl[4];
            uint32_t wBase = smb + (uint32_t)(SA_TOT + buf*2*SW_BUF
                              + (i*16 + wrow)*SW_ROW + wk)*2;
            ldsm4(wh, wBase);
            ldsm4(wl, wBase + (uint32_t)SW_BUF*2);
#pragma unroll
            for (int t = 0; t < 2; t++) {
                mma16816(acc[t][2*i],   a_hi[t], wh[0], wh[1]);
                mma16816(acc[t][2*i],   a_hi[t], wl[0], wl[1]);
                mma16816(acc[t][2*i],   a_lo[t], wh[0], wh[1]);
                mma16816(acc[t][2*i+1], a_hi[t], wh[2], wh[3]);
                mma16816(acc[t][2*i+1], a_hi[t], wl[2], wl[3]);
                mma16816(acc[t][2*i+1], a_lo[t], wh[2], wh[3]);
            }
        }
        // no trailing sync: next store targets buf^1, whose last readers were
        // chunk ch-1 (separated by this chunk's barrier).
    }

    float leak = *leak_ptr;
    leak = fminf(fmaxf(leak, 0.001f), 1000.0f);
#pragma unroll
    for (int t = 0; t < 2; t++) {
        int mr = px0 + w*32 + t*16 + (l >> 2);
#pragma unroll
        for (int nt = 0; nt < 8; nt++) {
            int o = nt*8 + (l & 3)*2;
            const float* po0 = embt  + (size_t)(b*NF + o)*HW;
            float*       pn0 = embt1 + (size_t)(b*NF + o)*HW;
            float bv0 = g_bias[b*NF + o];
            float bv1 = g_bias[b*NF + o + 1];
            pn0[mr]          = po0[mr]          + leak*(acc[t][nt][0] + bv0);
            pn0[mr + HW]     = po0[mr + HW]     + leak*(acc[t][nt][1] + bv1);
            pn0[mr + 8]      = po0[mr + 8]      + leak*(acc[t][nt][2] + bv0);
            pn0[mr + 8 + HW] = po0[mr + 8 + HW] + leak*(acc[t][nt][3] + bv1);
        }
    }
}

// clipped RGB + raw RGB from the final state
__global__ void k_final(const float* __restrict__ emb_final, float* __restrict__ out) {
    int idx = blockIdx.x * 256 + threadIdx.x;     // < 196608
    int b = idx / (3*HW);
    int rem = idx - b*3*HW;
    int c = rem >> 12;
    int px = rem & 4095;
    float v = emb_final[((size_t)(b*NF + c))*HW + px];
    out[(size_t)OFF_RAW + idx] = v;
    out[idx] = fminf(fmaxf(v, -1.0f), 1.0f);
}

// ---------------------------------------------------------------------------
extern "C" void kernel_launch(void* const* d_in, const int* in_sizes, int n_in,
                              void* d_out, int out_size) {
    const float* lat  = (const float*)d_in[0];
    const float* Wk   = (const float*)d_in[1];
    const float* bk   = (const float*)d_in[2];
    const float* Wb   = (const float*)d_in[3];
    const float* bb   = (const float*)d_in[4];
    const float* leak = (const float*)d_in[5];
    float* out = (float*)d_out;

    // ordering: harness issues 2 hidden launches first; ncu -s 5 -c 1 thus
    // profiles OUR launch #3 = the first k_gemm.
    k_init<<<EMB_SLICE/256, 256>>>(out + OFF_EMB);             // #0
    k_weights<<<49, 256>>>(lat, Wk, bk, Wb, bb);               // #1

    for (int t = 0; t < STEPS; t++) {
        const float* et  = out + (size_t)OFF_EMB + (size_t)t * EMB_SLICE;
        float*       et1 = out + (size_t)OFF_EMB + (size_t)(t + 1) * EMB_SLICE;
        k_stats<<<dim3(64, 16), 512>>>(et);                    // #2, #4, ...
        k_gemm<<<dim3(16, 16), 256>>>(et, et1, leak);          // #3  <- ncu target
    }
    k_final<<<N_CLIP/256, 256>>>(out + OFF_EMB + (size_t)16*EMB_SLICE, out);
}